// round 4
// baseline (speedup 1.0000x reference)
#include <cuda_runtime.h>
#include <math.h>

#define NB 128
#define NP 8732
#define NM 16
#define NC 21
#define LBLK 128
#define NLB ((NP + LBLK - 1) / LBLK)   // 69

// ---------------- scratch (self-cleaning across replays; static zero-init for first run) ----------------
__device__ float    g_confneg[NB * NP];
__device__ unsigned long long g_best[NB * NM];
__device__ int    g_npos[NB];
__device__ int    g_npos_total;
__device__ double g_loc_sum;
__device__ double g_pos_sum;
__device__ double g_hard_sum;
__device__ int    g_done;

// ---------------- shared numeric helpers (bitwise-identical in fused & fixup) ----------------
__device__ __forceinline__ float ce_lse(const float* sv) {
    float mx = sv[0];
    #pragma unroll
    for (int c = 1; c < NC; c++) mx = fmaxf(mx, sv[c]);
    float se = 0.0f;
    #pragma unroll
    for (int c = 0; c < NC; c++) se += __expf(sv[c] - mx);
    return __logf(se) + mx;
}

__device__ __forceinline__ float loc_l1(float4 bx, float4 pr, float4 pl) {
    float cx = 0.5f * (bx.x + bx.z);
    float cy = 0.5f * (bx.y + bx.w);
    float cw = bx.z - bx.x;
    float ch = bx.w - bx.y;
    float g0 = (cx - pr.x) * 10.0f / pr.z;
    float g1 = (cy - pr.y) * 10.0f / pr.w;
    float g2 = __logf(cw / pr.z) * 5.0f;
    float g3 = __logf(ch / pr.w) * 5.0f;
    return fabsf(pl.x - g0) + fabsf(pl.y - g1) + fabsf(pl.z - g2) + fabsf(pl.w - g3);
}

// ---------------- fused match + loss ----------------
// grid (69, 128), block 128.
__global__ void __launch_bounds__(128) fused_kernel(
        const float4* __restrict__ plocs,
        const float*  __restrict__ scores,
        const float4* __restrict__ boxes,
        const int*    __restrict__ labels,
        const float4* __restrict__ priors) {
    __shared__ float4 sbox[NM];
    __shared__ float  sarea[NM];
    __shared__ int    slab[NM];
    __shared__ unsigned skey[NM][LBLK];     // 8 KB
    __shared__ float  ssc[LBLK * NC];       // 10.75 KB
    __shared__ float  rl[4], rp[4];
    __shared__ int    rc[4];

    int b = blockIdx.y;
    int base = blockIdx.x * LBLK;
    int tid = threadIdx.x;
    int nval = NP - base; if (nval > LBLK) nval = LBLK;

    // fire-and-forget score staging; (nval*21) % 4 == 0 always, base 16B-aligned
    {
        const float4* src = (const float4*)(scores + ((size_t)b * NP + base) * NC);
        int nvec = (nval * NC) >> 2;
        for (int i = tid; i < nvec; i += LBLK) {
            unsigned sa = (unsigned)__cvta_generic_to_shared(&((float4*)ssc)[i]);
            asm volatile("cp.async.cg.shared.global [%0], [%1], 16;" :: "r"(sa), "l"(src + i));
        }
        asm volatile("cp.async.commit_group;");
    }

    if (tid < NM) {
        float4 bx = __ldg(&boxes[b * NM + tid]);
        sbox[tid] = bx;
        sarea[tid] = (bx.z - bx.x) * (bx.w - bx.y);
        slab[tid] = labels[b * NM + tid];
    }
    __syncthreads();

    int p = base + tid;
    bool valid = (tid < nval);

    float bestv = -1.0f;
    int   bestm = 0;
    float4 pr = make_float4(0.f, 0.f, 1.f, 1.f);
    if (valid) pr = __ldg(&priors[p]);
    {
        float px1 = pr.x - 0.5f * pr.z;
        float py1 = pr.y - 0.5f * pr.w;
        float px2 = pr.x + 0.5f * pr.z;
        float py2 = pr.y + 0.5f * pr.w;
        float pa  = pr.z * pr.w;
        #pragma unroll
        for (int m = 0; m < NM; m++) {
            float iou = 0.0f;
            if (valid) {
                float4 bx = sbox[m];
                float lx = fmaxf(bx.x, px1), ly = fmaxf(bx.y, py1);
                float rx = fminf(bx.z, px2), ry = fminf(bx.w, py2);
                float w = fmaxf(rx - lx, 0.0f), h = fmaxf(ry - ly, 0.0f);
                float inter = w * h;
                iou = __fdividef(inter, sarea[m] + pa - inter);
            }
            skey[m][tid] = __float_as_uint(iou);
            if (iou > bestv) { bestv = iou; bestm = m; }   // strict >: lowest m on ties
        }
    }
    __syncthreads();

    // per-object argmax over this tile -> global atomicMax (ties: lowest p)
    {
        int warp = tid >> 5, lane = tid & 31;
        #pragma unroll
        for (int mm = 0; mm < 4; mm++) {
            int m = warp * 4 + mm;
            unsigned long long best = 0ull;
            #pragma unroll
            for (int i = 0; i < 4; i++) {
                int idx = lane + i * 32;
                if (idx < nval) {
                    unsigned long long key = (((unsigned long long)skey[m][idx]) << 32)
                        | (unsigned long long)(0xFFFFFFFFu - (unsigned)(base + idx));
                    if (key > best) best = key;
                }
            }
            #pragma unroll
            for (int o = 16; o; o >>= 1) {
                unsigned long long other = __shfl_down_sync(0xFFFFFFFFu, best, o);
                if (other > best) best = other;
            }
            if (lane == 0) atomicMax(&g_best[b * NM + m], best);
        }
    }

    asm volatile("cp.async.wait_group 0;");
    __syncthreads();

    float locsum = 0.0f, possum = 0.0f;
    int cnt = 0;
    if (valid) {
        int idx = b * NP + p;
        int label = (bestv < 0.5f) ? 0 : slab[bestm];
        const float* sv = ssc + tid * NC;       // stride 21: conflict-free
        float lse = ce_lse(sv);
        float conf = lse - sv[label];
        if (label != 0) {
            cnt = 1;
            possum = conf;
            locsum = loc_l1(sbox[bestm], pr, __ldg(&plocs[idx]));
            g_confneg[idx] = 0.0f;
        } else {
            g_confneg[idx] = conf;
        }
    }

    int lane = tid & 31, warp = tid >> 5;
    #pragma unroll
    for (int o = 16; o; o >>= 1) {
        locsum += __shfl_down_sync(0xFFFFFFFFu, locsum, o);
        possum += __shfl_down_sync(0xFFFFFFFFu, possum, o);
        cnt    += __shfl_down_sync(0xFFFFFFFFu, cnt, o);
    }
    if (lane == 0) { rl[warp] = locsum; rp[warp] = possum; rc[warp] = cnt; }
    __syncthreads();
    if (tid == 0) {
        float L = rl[0] + rl[1] + rl[2] + rl[3];
        float Q = rp[0] + rp[1] + rp[2] + rp[3];
        int cc = rc[0] + rc[1] + rc[2] + rc[3];
        if (L != 0.0f) atomicAdd(&g_loc_sum, (double)L);
        if (Q != 0.0f) atomicAdd(&g_pos_sum, (double)Q);
        if (cc) {
            atomicAdd(&g_npos[b], cc);
            atomicAdd(&g_npos_total, cc);
        }
    }
}

// ---------------- bucket locate helper (warp 0 only) ----------------
__device__ __forceinline__ void find_bucket(const int* hist, int nbuckets, int k,
                                            int lane, int* fb) {
    int chunk = nbuckets >> 5;
    int base = lane * chunk;
    int cs = 0;
    for (int i = 0; i < chunk; i++) cs += hist[base + i];
    int incl = cs;
    #pragma unroll
    for (int o = 1; o < 32; o <<= 1) {
        int t = __shfl_down_sync(0xFFFFFFFFu, incl, o);
        if (lane + o < 32) incl += t;
    }
    int excl = incl - cs;
    bool hit = (excl < k) && (k <= incl);
    unsigned ball = __ballot_sync(0xFFFFFFFFu, hit);
    int j = __ffs(ball) - 1;
    if (lane == j) {
        int acc = excl;
        for (int i = chunk - 1; i >= 0; i--) {
            int h = hist[base + i];
            if (acc + h >= k) { fb[0] = base + i; fb[1] = k - acc; break; }
            acc += h;
        }
    }
}

// ---------------- fixup + hard-negative mining + final combine ----------------
__global__ void __launch_bounds__(1024, 1) hardneg_final_kernel(
        const float4* __restrict__ plocs,
        const float*  __restrict__ scores,
        const float4* __restrict__ boxes,
        const int*    __restrict__ labels,
        const float4* __restrict__ priors,
        float* __restrict__ out) {
    __shared__ unsigned v[NP];        // 34928 B
    __shared__ int hist[2048];        // 8192 B
    __shared__ int fb[2];
    __shared__ double sred[32];
    __shared__ int red[32];
    __shared__ int s_flist[NM];
    __shared__ int s_fcnt;
    __shared__ int s_npos;

    int b = blockIdx.x;
    int tid = threadIdx.x;
    int lane = tid & 31, warp = tid >> 5;

    if (warp == 0) {
        // ---- fixup: force-assign deltas for <=16 priors of this row ----
        int p = -1;
        if (lane < NM) {
            unsigned long long kb = g_best[b * NM + lane];
            p = (int)(0xFFFFFFFFu - (unsigned)(kb & 0xFFFFFFFFull));
            g_best[b * NM + lane] = 0ull;     // self-clean for next replay
        }
        bool active = (lane < NM);
        #pragma unroll
        for (int o = 0; o < NM; o++) {        // dedupe: last m wins (scatter semantics)
            int po = __shfl_sync(0xFFFFFFFFu, p, o);
            if (o > lane && po == p) active = false;
        }
        float d_loc = 0.0f, d_pos = 0.0f;
        int d_np = 0;
        if (active) {
            // recompute fused's assignment for prior p (bitwise-identical math)
            float4 pr = __ldg(&priors[p]);
            float px1 = pr.x - 0.5f * pr.z;
            float py1 = pr.y - 0.5f * pr.w;
            float px2 = pr.x + 0.5f * pr.z;
            float py2 = pr.y + 0.5f * pr.w;
            float pa  = pr.z * pr.w;
            float bestv = -1.0f; int bestm = 0;
            #pragma unroll
            for (int m = 0; m < NM; m++) {
                float4 bx = __ldg(&boxes[b * NM + m]);
                float sa = (bx.z - bx.x) * (bx.w - bx.y);
                float lx = fmaxf(bx.x, px1), ly = fmaxf(bx.y, py1);
                float rx = fminf(bx.z, px2), ry = fminf(bx.w, py2);
                float w = fmaxf(rx - lx, 0.0f), h = fmaxf(ry - ly, 0.0f);
                float inter = w * h;
                float iou = __fdividef(inter, sa + pa - inter);
                if (iou > bestv) { bestv = iou; bestm = m; }
            }
            int label_old = (bestv < 0.5f) ? 0 : labels[b * NM + bestm];
            int label_new = labels[b * NM + lane];    // >= 1
            float sv[NC];
            const float* s = scores + (size_t)(b * NP + p) * NC;
            #pragma unroll
            for (int c = 0; c < NC; c++) sv[c] = s[c];
            float4 pl = __ldg(&plocs[b * NP + p]);
            float loc_new = loc_l1(__ldg(&boxes[b * NM + lane]), pr, pl);
            if (label_old != 0) {
                d_pos = sv[label_old] - sv[label_new];     // lse cancels
                d_loc = loc_new - loc_l1(__ldg(&boxes[b * NM + bestm]), pr, pl);
            } else {
                d_pos = ce_lse(sv) - sv[label_new];
                d_loc = loc_new;
                d_np = 1;
            }
        }
        unsigned fm = __ballot_sync(0xFFFFFFFFu, d_np != 0);
        if (d_np) s_flist[__popc(fm & ((1u << lane) - 1))] = p;
        float rloc = d_loc, rpos = d_pos;
        int rnp = d_np;
        #pragma unroll
        for (int o = 16; o; o >>= 1) {
            rloc += __shfl_down_sync(0xFFFFFFFFu, rloc, o);
            rpos += __shfl_down_sync(0xFFFFFFFFu, rpos, o);
            rnp  += __shfl_down_sync(0xFFFFFFFFu, rnp, o);
        }
        if (lane == 0) {
            s_fcnt = __popc(fm);
            if (rloc != 0.0f) atomicAdd(&g_loc_sum, (double)rloc);
            if (rpos != 0.0f) atomicAdd(&g_pos_sum, (double)rpos);
            if (rnp) atomicAdd(&g_npos_total, rnp);
            int np = g_npos[b];
            g_npos[b] = 0;                    // self-clean
            s_npos = np + rnp;
        }
    } else {
        // ---- warps 1..31: load the negative pool + zero hist (overlaps fixup) ----
        for (int i = tid - 32; i < NP; i += 992)
            v[i] = __float_as_uint(g_confneg[b * NP + i]);
        for (int i = tid - 32; i < 2048; i += 992)
            hist[i] = 0;
    }
    __syncthreads();
    if (tid < s_fcnt) v[s_flist[tid]] = 0u;   // forced positives leave negative pool
    __syncthreads();

    int k = 3 * s_npos;
    if (k > NP) k = NP;

    // ---- level 1: top 11 bits, warp-aggregated atomics ----
    #pragma unroll
    for (int j = 0; j < 9; j++) {
        int i = tid + j * 1024;
        unsigned am = __ballot_sync(0xFFFFFFFFu, i < NP);
        if (i < NP) {
            unsigned bkt = v[i] >> 20;
            unsigned mm = __match_any_sync(am, bkt);
            if ((int)(__ffs(mm) - 1) == lane) atomicAdd(&hist[bkt], __popc(mm));
        }
    }
    __syncthreads();
    if (warp == 0) find_bucket(hist, 2048, k, lane, fb);
    __syncthreads();
    unsigned B1 = (unsigned)fb[0];
    int r = fb[1];
    for (int i = tid; i < 2048; i += 1024) hist[i] = 0;
    __syncthreads();

    // ---- level 2: next 11 bits among bucket B1 (few matches; direct atomics) ----
    #pragma unroll
    for (int j = 0; j < 9; j++) {
        int i = tid + j * 1024;
        if (i < NP) {
            unsigned x = v[i];
            if ((x >> 20) == B1) atomicAdd(&hist[(x >> 9) & 0x7FFu], 1);
        }
    }
    __syncthreads();
    if (warp == 0) find_bucket(hist, 2048, r, lane, fb);
    __syncthreads();
    unsigned pfx = (B1 << 11) | (unsigned)fb[0];
    r = fb[1];
    for (int i = tid; i < 512; i += 1024) hist[i] = 0;
    __syncthreads();

    // ---- level 3: low 9 bits among prefix pfx ----
    #pragma unroll
    for (int j = 0; j < 9; j++) {
        int i = tid + j * 1024;
        if (i < NP) {
            unsigned x = v[i];
            if ((x >> 9) == pfx) atomicAdd(&hist[x & 0x1FFu], 1);
        }
    }
    __syncthreads();
    if (warp == 0) find_bucket(hist, 512, r, lane, fb);
    __syncthreads();
    unsigned thr = (pfx << 9) | (unsigned)fb[0];   // exact kth-largest bit pattern

    // ---- exact top-k sum: strictly greater + tie copies of thr ----
    double s = 0.0;
    int c = 0;
    #pragma unroll
    for (int j = 0; j < 9; j++) {
        int i = tid + j * 1024;
        if (i < NP) {
            unsigned x = v[i];
            if (x > thr) { s += (double)__uint_as_float(x); c++; }
        }
    }
    #pragma unroll
    for (int o = 16; o; o >>= 1) {
        s += __shfl_down_sync(0xFFFFFFFFu, s, o);
        c += __shfl_down_sync(0xFFFFFFFFu, c, o);
    }
    if (lane == 0) { sred[warp] = s; red[warp] = c; }
    __syncthreads();
    if (warp == 0) {
        double S = sred[lane];
        int C = red[lane];
        #pragma unroll
        for (int o = 16; o; o >>= 1) {
            S += __shfl_down_sync(0xFFFFFFFFu, S, o);
            C += __shfl_down_sync(0xFFFFFFFFu, C, o);
        }
        if (lane == 0) {
            atomicAdd(&g_hard_sum, S + (double)(k - C) * (double)__uint_as_float(thr));
            __threadfence();
            if (atomicAdd(&g_done, 1) == NB - 1) {
                __threadfence();
                // coherent reads via atomic RMW (L1 not coherent within a launch)
                int nt = atomicAdd(&g_npos_total, 0);
                double hs = atomicAdd(&g_hard_sum, 0.0);
                double ps = atomicAdd(&g_pos_sum, 0.0);
                double ls = atomicAdd(&g_loc_sum, 0.0);
                double conf_loss = (hs + ps) / (double)nt;
                long long dd = 4LL * (long long)nt;
                if (dd < 1) dd = 1;
                out[0] = (float)(conf_loss + ls / (double)dd);
                // self-clean for next replay
                g_npos_total = 0;
                g_loc_sum = 0.0;
                g_pos_sum = 0.0;
                g_hard_sum = 0.0;
                g_done = 0;
            }
        }
    }
}

// ---------------- launch ----------------
extern "C" void kernel_launch(void* const* d_in, const int* in_sizes, int n_in,
                              void* d_out, int out_size) {
    const float* plocs  = (const float*)d_in[0];  // [B,P,4]
    const float* scores = (const float*)d_in[1];  // [B,P,C]
    const float* boxes  = (const float*)d_in[2];  // [B,M,4]
    const int*   labels = (const int*)d_in[3];    // [B,M]
    const float* priors = (const float*)d_in[4];  // [P,4]

    dim3 g(NLB, NB);
    fused_kernel<<<g, LBLK>>>((const float4*)plocs, scores,
                              (const float4*)boxes, labels,
                              (const float4*)priors);
    hardneg_final_kernel<<<NB, 1024>>>((const float4*)plocs, scores,
                                       (const float4*)boxes, labels,
                                       (const float4*)priors, (float*)d_out);
}